// round 3
// baseline (speedup 1.0000x reference)
#include <cuda_runtime.h>
#include <math.h>

#define NN 100000
#define EE 800000
#define H  32
#define NL 4
#define FULL 0xffffffffu

// ---------------- scratch (device globals; all edge state in dst-sorted order) ----
__device__ float g_h[NN*H];
__device__ float g_e[EE*H];        // sorted
__device__ float g_enew[EE*H];     // sorted
__device__ float g_Ah[NN*H];       // reused as hid_src for score
__device__ float g_Bh[NN*H];       // reused as hid_dst for score
__device__ float g_Uh[NN*H];
__device__ float g_Vh[NN*H];
__device__ float g_hnew[NN*H];
// [0:32) sum_h, [32:64) sq_h, [64:96) sum_e, [96:128) sq_e
__device__ float g_stats[128];
__device__ int   g_hist[NN+1];
__device__ int   g_rowptr[NN+1];
__device__ int   g_cursor[NN];
__device__ int   g_ssrc[EE];
__device__ int   g_sdst[EE];
__device__ int   g_oid[EE];

// ---------------- CSR build ------------------------------------------------------
__global__ void hist_kernel(const int* __restrict__ dst, int ne)
{
    for (int i = blockIdx.x * blockDim.x + threadIdx.x; i < ne;
         i += gridDim.x * blockDim.x)
        atomicAdd(&g_hist[dst[i]], 1);
}

// single block, 1024 threads: exclusive scan of g_hist[0..NN] -> rowptr, cursor
__global__ void scan_kernel()
{
    __shared__ int sm[1024];
    const int n = NN + 1;
    const int SEG = (n + 1023) / 1024;
    int tid = threadIdx.x;
    int base = tid * SEG;
    int s = 0;
    for (int i = base; i < base + SEG && i < n; i++) s += g_hist[i];
    sm[tid] = s;
    __syncthreads();
    for (int off = 1; off < 1024; off <<= 1) {
        int t = (tid >= off) ? sm[tid - off] : 0;
        __syncthreads();
        sm[tid] += t;
        __syncthreads();
    }
    int run = sm[tid] - s;  // exclusive prefix of this segment
    for (int i = base; i < base + SEG && i < n; i++) {
        int c = g_hist[i];
        g_rowptr[i] = run;
        if (i < NN) g_cursor[i] = run;
        run += c;
    }
}

__global__ void scatter_kernel(const int* __restrict__ src, const int* __restrict__ dst,
                               int ne)
{
    for (int i = blockIdx.x * blockDim.x + threadIdx.x; i < ne;
         i += gridDim.x * blockDim.x) {
        int d = dst[i];
        int pos = atomicAdd(&g_cursor[d], 1);
        g_ssrc[pos] = src[i];
        g_sdst[pos] = d;
        g_oid[pos]  = i;
    }
}

// ---------------- input projections ----------------------------------------------
__global__ void proj_h(const float* __restrict__ x, const float* __restrict__ w,
                       const float* __restrict__ b, int n)
{
    int total = n * H;
    for (int t = blockIdx.x * blockDim.x + threadIdx.x; t < total;
         t += gridDim.x * blockDim.x) {
        int row = t >> 5, lane = t & 31;
        g_h[t] = x[row] * w[lane] + b[lane];
    }
}

__global__ void proj_e(const float* __restrict__ ein, const float* __restrict__ w,
                       const float* __restrict__ b, int ne)
{
    int total = ne * H;
    for (int t = blockIdx.x * blockDim.x + threadIdx.x; t < total;
         t += gridDim.x * blockDim.x) {
        int row = t >> 5, lane = t & 31;
        g_e[t] = ein[g_oid[row]] * w[lane] + b[lane];
    }
}

// ---------------- 4 fused node GEMMs ---------------------------------------------
__global__ void node_gemm4(const float* __restrict__ Aw, const float* __restrict__ Ab,
                           const float* __restrict__ Bw, const float* __restrict__ Bb,
                           const float* __restrict__ Uw, const float* __restrict__ Ub,
                           const float* __restrict__ Vw, const float* __restrict__ Vb,
                           int n)
{
    __shared__ float wA[H*H], wB[H*H], wU[H*H], wV[H*H];
    __shared__ float bA[H], bB[H], bU[H], bV[H];
    for (int i = threadIdx.x; i < H*H; i += blockDim.x) {
        wA[i] = Aw[i]; wB[i] = Bw[i]; wU[i] = Uw[i]; wV[i] = Vw[i];
    }
    if (threadIdx.x < H) {
        bA[threadIdx.x] = Ab[threadIdx.x];
        bB[threadIdx.x] = Bb[threadIdx.x];
        bU[threadIdx.x] = Ub[threadIdx.x];
        bV[threadIdx.x] = Vb[threadIdx.x];
    }
    __syncthreads();

    int lane = threadIdx.x & 31;
    int warp = threadIdx.x >> 5;
    int wpb  = blockDim.x >> 5;
    int stride = gridDim.x * wpb;
    for (int row = blockIdx.x * wpb + warp; row < n; row += stride) {
        float hv = g_h[row*H + lane];
        float a = bA[lane], b = bB[lane], u = bU[lane], v = bV[lane];
        #pragma unroll
        for (int k = 0; k < H; k++) {
            float hk = __shfl_sync(FULL, hv, k);
            a += hk * wA[k*H + lane];
            b += hk * wB[k*H + lane];
            u += hk * wU[k*H + lane];
            v += hk * wV[k*H + lane];
        }
        g_Ah[row*H + lane] = a;
        g_Bh[row*H + lane] = b;
        g_Uh[row*H + lane] = u;
        g_Vh[row*H + lane] = v;
    }
}

// ---- fused aggregation: warp per node, NO atomics; Ce GEMM + e_new + sigma +
// ---- gated mean + hnew + both BN stat accumulations --------------------------
__global__ void agg_kernel(const float* __restrict__ Cw, const float* __restrict__ Cb,
                           int n)
{
    int lane = threadIdx.x & 31;
    float wC[32];
    #pragma unroll
    for (int k = 0; k < 32; k++) wC[k] = Cw[k*H + lane];
    float bC = Cb[lane];

    __shared__ float sE[32], qE[32], sH[32], qH[32];
    if (threadIdx.x < 32) {
        sE[threadIdx.x] = 0.f; qE[threadIdx.x] = 0.f;
        sH[threadIdx.x] = 0.f; qH[threadIdx.x] = 0.f;
    }
    __syncthreads();

    float ls = 0.f, lq = 0.f, hs = 0.f, hq = 0.f;
    int warp = threadIdx.x >> 5;
    int wpb  = blockDim.x >> 5;
    int stride = gridDim.x * wpb;
    for (int d = blockIdx.x * wpb + warp; d < n; d += stride) {
        int beg = g_rowptr[d], end = g_rowptr[d+1];
        float ah = g_Ah[d*H + lane];
        float uh = g_Uh[d*H + lane];
        float num = 0.f, den = 0.f;
        for (int i = beg; i < end; i++) {
            int s = g_ssrc[i];
            float ev = g_e[i*H + lane];
            float ce = bC;
            #pragma unroll
            for (int k = 0; k < 32; k++)
                ce += __shfl_sync(FULL, ev, k) * wC[k];
            float enew = ah + g_Bh[s*H + lane] + ce;
            g_enew[i*H + lane] = enew;
            ls += enew; lq += enew * enew;
            float sig = 1.0f / (1.0f + __expf(-enew));
            num += sig * g_Vh[s*H + lane];
            den += sig;
        }
        float hn = uh + num / (den + 1e-6f);
        g_hnew[d*H + lane] = hn;
        hs += hn; hq += hn * hn;
    }
    atomicAdd(&sH[lane], hs); atomicAdd(&qH[lane], hq);
    atomicAdd(&sE[lane], ls); atomicAdd(&qE[lane], lq);
    __syncthreads();
    if (threadIdx.x < 32) {
        atomicAdd(&g_stats[threadIdx.x],      sH[threadIdx.x]);
        atomicAdd(&g_stats[32 + threadIdx.x], qH[threadIdx.x]);
        atomicAdd(&g_stats[64 + threadIdx.x], sE[threadIdx.x]);
        atomicAdd(&g_stats[96 + threadIdx.x], qE[threadIdx.x]);
    }
}

// ---------------- h += relu(BN(hnew)), float4 --------------------------------------
__global__ void node_update(const float* __restrict__ gamma, const float* __restrict__ beta,
                            int n)
{
    __shared__ float mn[32], sc[32], bt[32];
    if (threadIdx.x < 32) {
        float inv = 1.0f / (float)n;
        float mean = g_stats[threadIdx.x] * inv;
        float var  = g_stats[32 + threadIdx.x] * inv - mean * mean;
        mn[threadIdx.x] = mean;
        sc[threadIdx.x] = rsqrtf(var + 1e-5f) * gamma[threadIdx.x];
        bt[threadIdx.x] = beta[threadIdx.x];
    }
    __syncthreads();
    int tot = n * (H/4);
    const float4* vin = (const float4*)g_hnew;
    float4* hout = (float4*)g_h;
    for (int t = blockIdx.x * blockDim.x + threadIdx.x; t < tot;
         t += gridDim.x * blockDim.x) {
        int l4 = (t & 7) * 4;
        float4 v = vin[t];
        float4 hv = hout[t];
        hv.x += fmaxf((v.x - mn[l4+0]) * sc[l4+0] + bt[l4+0], 0.f);
        hv.y += fmaxf((v.y - mn[l4+1]) * sc[l4+1] + bt[l4+1], 0.f);
        hv.z += fmaxf((v.z - mn[l4+2]) * sc[l4+2] + bt[l4+2], 0.f);
        hv.w += fmaxf((v.w - mn[l4+3]) * sc[l4+3] + bt[l4+3], 0.f);
        hout[t] = hv;
    }
}

// ---------------- e += relu(BN(e_new)), float4 -------------------------------------
__global__ void edge_update(const float* __restrict__ gamma, const float* __restrict__ beta,
                            int ne)
{
    __shared__ float mn[32], sc[32], bt[32];
    if (threadIdx.x < 32) {
        float inv = 1.0f / (float)ne;
        float mean = g_stats[64 + threadIdx.x] * inv;
        float var  = g_stats[96 + threadIdx.x] * inv - mean * mean;
        mn[threadIdx.x] = mean;
        sc[threadIdx.x] = rsqrtf(var + 1e-5f) * gamma[threadIdx.x];
        bt[threadIdx.x] = beta[threadIdx.x];
    }
    __syncthreads();
    int tot = ne * (H/4);
    const float4* vin = (const float4*)g_enew;
    float4* eout = (float4*)g_e;
    for (int t = blockIdx.x * blockDim.x + threadIdx.x; t < tot;
         t += gridDim.x * blockDim.x) {
        int l4 = (t & 7) * 4;
        float4 v = vin[t];
        float4 ev = eout[t];
        ev.x += fmaxf((v.x - mn[l4+0]) * sc[l4+0] + bt[l4+0], 0.f);
        ev.y += fmaxf((v.y - mn[l4+1]) * sc[l4+1] + bt[l4+1], 0.f);
        ev.z += fmaxf((v.z - mn[l4+2]) * sc[l4+2] + bt[l4+2], 0.f);
        ev.w += fmaxf((v.w - mn[l4+3]) * sc[l4+3] + bt[l4+3], 0.f);
        eout[t] = ev;
    }
}

// ---- score pre-pass: hid_src = h@W1[0:32]+b1 -> g_Ah ; hid_dst = h@W1[32:64] -> g_Bh
__global__ void score_gemm2(const float* __restrict__ W1, const float* __restrict__ b1,
                            int n)
{
    int lane = threadIdx.x & 31;
    float ws[32], wd[32];
    #pragma unroll
    for (int k = 0; k < 32; k++) {
        ws[k] = W1[k*32 + lane];
        wd[k] = W1[(32 + k)*32 + lane];
    }
    float bb = b1[lane];

    int warp = threadIdx.x >> 5;
    int wpb  = blockDim.x >> 5;
    int stride = gridDim.x * wpb;
    for (int row = blockIdx.x * wpb + warp; row < n; row += stride) {
        float hv = g_h[row*H + lane];
        float a = bb, c = 0.f;
        #pragma unroll
        for (int k = 0; k < 32; k++) {
            float hk = __shfl_sync(FULL, hv, k);
            a += hk * ws[k];
            c += hk * wd[k];
        }
        g_Ah[row*H + lane] = a;
        g_Bh[row*H + lane] = c;
    }
}

// ---------------- score: relu(hid_s[s]+hid_d[d]+e@W1e) @ W2 + b2 ------------------
__global__ void score_kernel(const float* __restrict__ W1e,
                             const float* __restrict__ W2, const float* __restrict__ b2,
                             float* __restrict__ out, int ne)
{
    int lane = threadIdx.x & 31;
    float we[32];
    #pragma unroll
    for (int k = 0; k < 32; k++) we[k] = W1e[k*32 + lane];
    float w2 = W2[lane];
    float bb2 = b2[0];

    int warp = threadIdx.x >> 5;
    int wpb  = blockDim.x >> 5;
    int stride = gridDim.x * wpb;
    for (int i = blockIdx.x * wpb + warp; i < ne; i += stride) {
        int s = g_ssrc[i], d = g_sdst[i], o = g_oid[i];
        float ze = g_e[i*H + lane];
        float hid = g_Ah[s*H + lane] + g_Bh[d*H + lane];
        #pragma unroll
        for (int k = 0; k < 32; k++)
            hid += __shfl_sync(FULL, ze, k) * we[k];
        hid = fmaxf(hid, 0.f);
        float p = hid * w2;
        #pragma unroll
        for (int off = 16; off > 0; off >>= 1)
            p += __shfl_xor_sync(FULL, p, off);
        if (lane == 0) out[o] = p + bb2;
    }
}

// ==================================================================================
extern "C" void kernel_launch(void* const* d_in, const int* in_sizes, int n_in,
                              void* d_out, int out_size)
{
    const float* x    = (const float*)d_in[0];
    const float* ein  = (const float*)d_in[1];
    const int*   eidx = (const int*)  d_in[2];
    const float* pe_w = (const float*)d_in[3];
    const float* pe_b = (const float*)d_in[4];
    const float* ed_w = (const float*)d_in[5];
    const float* ed_b = (const float*)d_in[6];
    const float* A_w  = (const float*)d_in[7];
    const float* A_b  = (const float*)d_in[8];
    const float* B_w  = (const float*)d_in[9];
    const float* B_b  = (const float*)d_in[10];
    const float* C_w  = (const float*)d_in[11];
    const float* C_b  = (const float*)d_in[12];
    const float* U_w  = (const float*)d_in[13];
    const float* U_b  = (const float*)d_in[14];
    const float* V_w  = (const float*)d_in[15];
    const float* V_b  = (const float*)d_in[16];
    const float* bnhg = (const float*)d_in[17];
    const float* bnhb = (const float*)d_in[18];
    const float* bneg = (const float*)d_in[19];
    const float* bneb = (const float*)d_in[20];
    const float* W1_w = (const float*)d_in[21];
    const float* W1_b = (const float*)d_in[22];
    const float* W2_w = (const float*)d_in[23];
    const float* W2_b = (const float*)d_in[24];
    float* out = (float*)d_out;

    const int n  = in_sizes[0];
    const int ne = in_sizes[1];
    const int* src = eidx;
    const int* dst = eidx + ne;

    void *p_hist, *p_stats;
    cudaGetSymbolAddress(&p_hist,  g_hist);
    cudaGetSymbolAddress(&p_stats, g_stats);

    const int TB = 256;
    const int G_NODE  = 1024;   // element-stride node kernels
    const int G_EDGE  = 4096;   // element/warp-stride edge kernels
    const int G_NWARP = 4096;   // warp-per-node kernels

    // ---- CSR build (dst-sorted edge order) ----
    cudaMemsetAsync(p_hist, 0, (NN + 1) * sizeof(int));
    hist_kernel<<<1024, TB>>>(dst, ne);
    scan_kernel<<<1, 1024>>>();
    scatter_kernel<<<1024, TB>>>(src, dst, ne);

    // ---- input projections ----
    proj_h<<<G_NODE, TB>>>(x, pe_w, pe_b, n);
    proj_e<<<G_EDGE, TB>>>(ein, ed_w, ed_b, ne);

    for (int l = 0; l < NL; l++) {
        cudaMemsetAsync(p_stats, 0, 128 * sizeof(float));

        node_gemm4<<<G_NWARP, TB>>>(A_w + l*H*H, A_b + l*H,
                                    B_w + l*H*H, B_b + l*H,
                                    U_w + l*H*H, U_b + l*H,
                                    V_w + l*H*H, V_b + l*H, n);

        agg_kernel<<<G_NWARP, TB>>>(C_w + l*H*H, C_b + l*H, n);

        node_update<<<G_NODE, TB>>>(bnhg + l*H, bnhb + l*H, n);
        edge_update<<<G_EDGE, TB>>>(bneg + l*H, bneb + l*H, ne);
    }

    score_gemm2<<<G_NWARP, TB>>>(W1_w, W1_b, n);
    score_kernel<<<G_EDGE, TB>>>(W1_w + 64*32, W2_w, W2_b, out, ne);
}

// round 4
// speedup vs baseline: 1.3115x; 1.3115x over previous
#include <cuda_runtime.h>
#include <cuda_fp16.h>
#include <math.h>

#define NN 100000
#define EE 800000
#define H  32
#define NL 4
#define FULL 0xffffffffu
#define SCAN_N   (NN + 1)
#define SCAN_NB  ((SCAN_N + 1023) / 1024)

// ---------------- scratch ---------------------------------------------------------
__device__ float  g_h[NN*H];
__device__ float  g_hnew[NN*H];
__device__ float  g_Ah[NN*H];
__device__ float  g_Bh[NN*H];
__device__ float  g_Uh[NN*H];
__device__ float  g_Vh[NN*H];
__device__ __half g_e[EE*H];       // e_l (dst-sorted), updated in place by agg_l
__device__ __half g_enew[EE*H];    // enew_l (dst-sorted), updated in place by agg_l
// stats slots: per layer l: [l*128 + 0:64) h sum/sq, [l*128+64:128) e sum/sq
__device__ float  g_stats[NL*128];
__device__ int    g_hist[SCAN_NB*1024];
__device__ int    g_rowptr[NN+1];
__device__ int    g_cursor[NN];
__device__ int    g_bsum[SCAN_NB];
__device__ int    g_boff[SCAN_NB];
__device__ int    g_ssrc[EE];
__device__ int    g_oid[EE];

// ---------------- CSR build -------------------------------------------------------
__global__ void hist_kernel(const int* __restrict__ dst, int ne)
{
    for (int i = blockIdx.x * blockDim.x + threadIdx.x; i < ne;
         i += gridDim.x * blockDim.x)
        atomicAdd(&g_hist[dst[i]], 1);
}

__global__ void scanA()   // per-block sums of hist
{
    __shared__ int sm[1024];
    int idx = blockIdx.x * 1024 + threadIdx.x;
    int v = (idx < SCAN_N) ? g_hist[idx] : 0;
    sm[threadIdx.x] = v;
    __syncthreads();
    for (int off = 512; off > 0; off >>= 1) {
        if (threadIdx.x < off) sm[threadIdx.x] += sm[threadIdx.x + off];
        __syncthreads();
    }
    if (threadIdx.x == 0) g_bsum[blockIdx.x] = sm[0];
}

__global__ void scanB()   // exclusive scan of block sums (1 block)
{
    __shared__ int sm[128];
    int t = threadIdx.x;
    sm[t] = (t < SCAN_NB) ? g_bsum[t] : 0;
    __syncthreads();
    for (int off = 1; off < 128; off <<= 1) {
        int v = (t >= off) ? sm[t - off] : 0;
        __syncthreads();
        sm[t] += v;
        __syncthreads();
    }
    if (t < SCAN_NB) g_boff[t] = sm[t] - g_bsum[t];   // exclusive
}

__global__ void scanC()   // local exclusive scan + block offset -> rowptr, cursor
{
    __shared__ int sm[1024];
    int idx = blockIdx.x * 1024 + threadIdx.x;
    int t = threadIdx.x;
    int v = (idx < SCAN_N) ? g_hist[idx] : 0;
    sm[t] = v;
    __syncthreads();
    for (int off = 1; off < 1024; off <<= 1) {
        int u = (t >= off) ? sm[t - off] : 0;
        __syncthreads();
        sm[t] += u;
        __syncthreads();
    }
    if (idx < SCAN_N) {
        int excl = sm[t] - v + g_boff[blockIdx.x];
        g_rowptr[idx] = excl;
        if (idx < NN) g_cursor[idx] = excl;
    }
}

__global__ void scatter_kernel(const int* __restrict__ src, const int* __restrict__ dst,
                               int ne)
{
    for (int i = blockIdx.x * blockDim.x + threadIdx.x; i < ne;
         i += gridDim.x * blockDim.x) {
        int d = dst[i];
        int pos = atomicAdd(&g_cursor[d], 1);
        g_ssrc[pos] = src[i];
        g_oid[pos]  = i;
    }
}

// ---------------- input projections -----------------------------------------------
__global__ void proj_h(const float* __restrict__ x, const float* __restrict__ w,
                       const float* __restrict__ b, int n)
{
    int total = n * H;
    for (int t = blockIdx.x * blockDim.x + threadIdx.x; t < total;
         t += gridDim.x * blockDim.x) {
        int row = t >> 5, lane = t & 31;
        g_h[t] = x[row] * w[lane] + b[lane];
    }
}

__global__ void proj_e(const float* __restrict__ ein, const float* __restrict__ w,
                       const float* __restrict__ b, int ne)
{
    int total = ne * H;
    for (int t = blockIdx.x * blockDim.x + threadIdx.x; t < total;
         t += gridDim.x * blockDim.x) {
        int row = t >> 5, lane = t & 31;
        g_e[t] = __float2half_rn(ein[g_oid[row]] * w[lane] + b[lane]);
    }
}

// ------- gemm4, with h-update of previous layer fused (l>=1) ----------------------
__global__ void gemm4_fused(const float* __restrict__ Aw, const float* __restrict__ Ab,
                            const float* __restrict__ Bw, const float* __restrict__ Bb,
                            const float* __restrict__ Uw, const float* __restrict__ Ub,
                            const float* __restrict__ Vw, const float* __restrict__ Vb,
                            const float* __restrict__ bng, const float* __restrict__ bnb,
                            int statSlot, int applyUpd, int n)
{
    __shared__ float wA[H*H], wB[H*H], wU[H*H], wV[H*H];
    __shared__ float bA[H], bB[H], bU[H], bV[H];
    for (int i = threadIdx.x; i < H*H; i += blockDim.x) {
        wA[i] = Aw[i]; wB[i] = Bw[i]; wU[i] = Uw[i]; wV[i] = Vw[i];
    }
    if (threadIdx.x < H) {
        bA[threadIdx.x] = Ab[threadIdx.x];
        bB[threadIdx.x] = Bb[threadIdx.x];
        bU[threadIdx.x] = Ub[threadIdx.x];
        bV[threadIdx.x] = Vb[threadIdx.x];
    }
    __syncthreads();

    int lane = threadIdx.x & 31;
    float mn = 0.f, sc = 0.f, bt = 0.f;
    if (applyUpd) {
        float inv = 1.0f / (float)n;
        float s1 = g_stats[statSlot*128 + lane];
        float s2 = g_stats[statSlot*128 + 32 + lane];
        mn = s1 * inv;
        float var = s2 * inv - mn * mn;
        sc = rsqrtf(var + 1e-5f) * bng[lane];
        bt = bnb[lane];
    }

    int row = blockIdx.x * (blockDim.x >> 5) + (threadIdx.x >> 5);
    if (row >= n) return;
    float hv = g_h[row*H + lane];
    if (applyUpd) {
        float v = (g_hnew[row*H + lane] - mn) * sc + bt;
        hv += fmaxf(v, 0.f);
        g_h[row*H + lane] = hv;
    }
    float a = bA[lane], b = bB[lane], u = bU[lane], v = bV[lane];
    #pragma unroll
    for (int k = 0; k < H; k++) {
        float hk = __shfl_sync(FULL, hv, k);
        a += hk * wA[k*H + lane];
        b += hk * wB[k*H + lane];
        u += hk * wU[k*H + lane];
        v += hk * wV[k*H + lane];
    }
    g_Ah[row*H + lane] = a;
    g_Bh[row*H + lane] = b;
    g_Uh[row*H + lane] = u;
    g_Vh[row*H + lane] = v;
}

// ---- fused aggregation: e-update of previous layer + Ce GEMM + e_new + sigma +
// ---- gated mean + hnew + BN stat accumulation. Warp per node, no atomics. --------
__global__ void agg_fused(const float* __restrict__ Cw, const float* __restrict__ Cb,
                          const float* __restrict__ bng, const float* __restrict__ bnb,
                          int prevSlot, int curSlot, int applyUpd, int n, float inv_ne)
{
    int lane = threadIdx.x & 31;
    float wC[32];
    #pragma unroll
    for (int k = 0; k < 32; k++) wC[k] = Cw[k*H + lane];
    float bC = Cb[lane];

    float mn = 0.f, sc = 0.f, bt = 0.f;
    if (applyUpd) {
        float s1 = g_stats[prevSlot*128 + 64 + lane];
        float s2 = g_stats[prevSlot*128 + 96 + lane];
        mn = s1 * inv_ne;
        float var = s2 * inv_ne - mn * mn;
        sc = rsqrtf(var + 1e-5f) * bng[lane];
        bt = bnb[lane];
    }

    __shared__ float sE[32], qE[32], sH[32], qH[32];
    if (threadIdx.x < 32) {
        sE[threadIdx.x] = 0.f; qE[threadIdx.x] = 0.f;
        sH[threadIdx.x] = 0.f; qH[threadIdx.x] = 0.f;
    }
    __syncthreads();

    float ls = 0.f, lq = 0.f, hs = 0.f, hq = 0.f;
    int d = blockIdx.x * (blockDim.x >> 5) + (threadIdx.x >> 5);
    if (d < n) {
        int beg = g_rowptr[d], end = g_rowptr[d+1];
        float ah = g_Ah[d*H + lane];
        float uh = g_Uh[d*H + lane];
        float num = 0.f, den = 0.f;
        int i = beg;
        for (; i + 1 < end; i += 2) {
            int s0 = g_ssrc[i], s1 = g_ssrc[i+1];
            float ev0 = __half2float(g_e[(size_t)i*H + lane]);
            float ev1 = __half2float(g_e[(size_t)(i+1)*H + lane]);
            if (applyUpd) {
                float en0 = __half2float(g_enew[(size_t)i*H + lane]);
                float en1 = __half2float(g_enew[(size_t)(i+1)*H + lane]);
                ev0 += fmaxf((en0 - mn) * sc + bt, 0.f);
                ev1 += fmaxf((en1 - mn) * sc + bt, 0.f);
                g_e[(size_t)i*H + lane]     = __float2half_rn(ev0);
                g_e[(size_t)(i+1)*H + lane] = __float2half_rn(ev1);
            }
            float bh0 = g_Bh[s0*H + lane], vh0 = g_Vh[s0*H + lane];
            float bh1 = g_Bh[s1*H + lane], vh1 = g_Vh[s1*H + lane];
            float ce0 = bC, ce1 = bC;
            #pragma unroll
            for (int k = 0; k < 32; k++) {
                ce0 += __shfl_sync(FULL, ev0, k) * wC[k];
                ce1 += __shfl_sync(FULL, ev1, k) * wC[k];
            }
            float enw0 = ah + bh0 + ce0;
            float enw1 = ah + bh1 + ce1;
            g_enew[(size_t)i*H + lane]     = __float2half_rn(enw0);
            g_enew[(size_t)(i+1)*H + lane] = __float2half_rn(enw1);
            ls += enw0 + enw1;
            lq += enw0 * enw0 + enw1 * enw1;
            float sg0 = 1.0f / (1.0f + __expf(-enw0));
            float sg1 = 1.0f / (1.0f + __expf(-enw1));
            num += sg0 * vh0 + sg1 * vh1;
            den += sg0 + sg1;
        }
        for (; i < end; i++) {
            int s0 = g_ssrc[i];
            float ev0 = __half2float(g_e[(size_t)i*H + lane]);
            if (applyUpd) {
                float en0 = __half2float(g_enew[(size_t)i*H + lane]);
                ev0 += fmaxf((en0 - mn) * sc + bt, 0.f);
                g_e[(size_t)i*H + lane] = __float2half_rn(ev0);
            }
            float ce0 = bC;
            #pragma unroll
            for (int k = 0; k < 32; k++)
                ce0 += __shfl_sync(FULL, ev0, k) * wC[k];
            float enw0 = ah + g_Bh[s0*H + lane] + ce0;
            g_enew[(size_t)i*H + lane] = __float2half_rn(enw0);
            ls += enw0; lq += enw0 * enw0;
            float sg0 = 1.0f / (1.0f + __expf(-enw0));
            num += sg0 * g_Vh[s0*H + lane];
            den += sg0;
        }
        float hn = uh + num / (den + 1e-6f);
        g_hnew[d*H + lane] = hn;
        hs += hn; hq += hn * hn;
    }
    atomicAdd(&sH[lane], hs); atomicAdd(&qH[lane], hq);
    atomicAdd(&sE[lane], ls); atomicAdd(&qE[lane], lq);
    __syncthreads();
    if (threadIdx.x < 32) {
        atomicAdd(&g_stats[curSlot*128 + threadIdx.x],      sH[threadIdx.x]);
        atomicAdd(&g_stats[curSlot*128 + 32 + threadIdx.x], qH[threadIdx.x]);
        atomicAdd(&g_stats[curSlot*128 + 64 + threadIdx.x], sE[threadIdx.x]);
        atomicAdd(&g_stats[curSlot*128 + 96 + threadIdx.x], qE[threadIdx.x]);
    }
}

// ---- score pre-pass: final h-update fused; hid_src -> g_Ah, hid_dst -> g_Bh ------
__global__ void score_gemm2(const float* __restrict__ W1, const float* __restrict__ b1,
                            const float* __restrict__ bng, const float* __restrict__ bnb,
                            int statSlot, int n)
{
    int lane = threadIdx.x & 31;
    float ws[32], wd[32];
    #pragma unroll
    for (int k = 0; k < 32; k++) {
        ws[k] = W1[k*32 + lane];
        wd[k] = W1[(32 + k)*32 + lane];
    }
    float bb = b1[lane];
    float inv = 1.0f / (float)n;
    float s1 = g_stats[statSlot*128 + lane];
    float s2 = g_stats[statSlot*128 + 32 + lane];
    float mn = s1 * inv;
    float var = s2 * inv - mn * mn;
    float sc = rsqrtf(var + 1e-5f) * bng[lane];
    float bt = bnb[lane];

    int row = blockIdx.x * (blockDim.x >> 5) + (threadIdx.x >> 5);
    if (row >= n) return;
    float hv = g_h[row*H + lane];
    hv += fmaxf((g_hnew[row*H + lane] - mn) * sc + bt, 0.f);
    float a = bb, c = 0.f;
    #pragma unroll
    for (int k = 0; k < 32; k++) {
        float hk = __shfl_sync(FULL, hv, k);
        a += hk * ws[k];
        c += hk * wd[k];
    }
    g_Ah[row*H + lane] = a;
    g_Bh[row*H + lane] = c;
}

// ---- score: final e-update fused; relu(hid_s+hid_d+e@W1e) @ W2 + b2 --------------
__global__ void score_kernel(const int* __restrict__ dst,
                             const float* __restrict__ W1e,
                             const float* __restrict__ W2, const float* __restrict__ b2,
                             const float* __restrict__ bng, const float* __restrict__ bnb,
                             int statSlot, float* __restrict__ out, int ne, float inv_ne)
{
    int lane = threadIdx.x & 31;
    float we[32];
    #pragma unroll
    for (int k = 0; k < 32; k++) we[k] = W1e[k*32 + lane];
    float w2 = W2[lane];
    float bb2 = b2[0];
    float s1 = g_stats[statSlot*128 + 64 + lane];
    float s2 = g_stats[statSlot*128 + 96 + lane];
    float mn = s1 * inv_ne;
    float var = s2 * inv_ne - mn * mn;
    float sc = rsqrtf(var + 1e-5f) * bng[lane];
    float bt = bnb[lane];

    int i = blockIdx.x * (blockDim.x >> 5) + (threadIdx.x >> 5);
    if (i >= ne) return;
    int s = g_ssrc[i], o = g_oid[i];
    int d = dst[o];
    float ze = __half2float(g_e[(size_t)i*H + lane]);
    float en = __half2float(g_enew[(size_t)i*H + lane]);
    ze += fmaxf((en - mn) * sc + bt, 0.f);
    float hid = g_Ah[s*H + lane] + g_Bh[d*H + lane];
    #pragma unroll
    for (int k = 0; k < 32; k++)
        hid += __shfl_sync(FULL, ze, k) * we[k];
    hid = fmaxf(hid, 0.f);
    float p = hid * w2;
    #pragma unroll
    for (int off = 16; off > 0; off >>= 1)
        p += __shfl_xor_sync(FULL, p, off);
    if (lane == 0) out[o] = p + bb2;
}

// ==================================================================================
extern "C" void kernel_launch(void* const* d_in, const int* in_sizes, int n_in,
                              void* d_out, int out_size)
{
    const float* x    = (const float*)d_in[0];
    const float* ein  = (const float*)d_in[1];
    const int*   eidx = (const int*)  d_in[2];
    const float* pe_w = (const float*)d_in[3];
    const float* pe_b = (const float*)d_in[4];
    const float* ed_w = (const float*)d_in[5];
    const float* ed_b = (const float*)d_in[6];
    const float* A_w  = (const float*)d_in[7];
    const float* A_b  = (const float*)d_in[8];
    const float* B_w  = (const float*)d_in[9];
    const float* B_b  = (const float*)d_in[10];
    const float* C_w  = (const float*)d_in[11];
    const float* C_b  = (const float*)d_in[12];
    const float* U_w  = (const float*)d_in[13];
    const float* U_b  = (const float*)d_in[14];
    const float* V_w  = (const float*)d_in[15];
    const float* V_b  = (const float*)d_in[16];
    const float* bnhg = (const float*)d_in[17];
    const float* bnhb = (const float*)d_in[18];
    const float* bneg = (const float*)d_in[19];
    const float* bneb = (const float*)d_in[20];
    const float* W1_w = (const float*)d_in[21];
    const float* W1_b = (const float*)d_in[22];
    const float* W2_w = (const float*)d_in[23];
    const float* W2_b = (const float*)d_in[24];
    float* out = (float*)d_out;

    const int n  = in_sizes[0];
    const int ne = in_sizes[1];
    const int* src = eidx;
    const int* dst = eidx + ne;
    const float inv_ne = 1.0f / (float)ne;

    void *p_hist, *p_stats;
    cudaGetSymbolAddress(&p_hist,  g_hist);
    cudaGetSymbolAddress(&p_stats, g_stats);

    const int TB = 256;
    const int WPB = TB / 32;
    const int G_NODE_W = (n  + WPB - 1) / WPB;   // warp-per-node
    const int G_EDGE_W = (ne + WPB - 1) / WPB;   // warp-per-edge

    // ---- CSR build (dst-sorted edge order) ----
    cudaMemsetAsync(p_hist,  0, SCAN_NB * 1024 * sizeof(int));
    cudaMemsetAsync(p_stats, 0, NL * 128 * sizeof(float));
    hist_kernel<<<800, TB>>>(dst, ne);
    scanA<<<SCAN_NB, 1024>>>();
    scanB<<<1, 128>>>();
    scanC<<<SCAN_NB, 1024>>>();
    scatter_kernel<<<800, TB>>>(src, dst, ne);

    // ---- input projections ----
    proj_h<<<1024, TB>>>(x, pe_w, pe_b, n);
    proj_e<<<4096, TB>>>(ein, ed_w, ed_b, ne);

    for (int l = 0; l < NL; l++) {
        gemm4_fused<<<G_NODE_W, TB>>>(A_w + l*H*H, A_b + l*H,
                                      B_w + l*H*H, B_b + l*H,
                                      U_w + l*H*H, U_b + l*H,
                                      V_w + l*H*H, V_b + l*H,
                                      bnhg + (l-1)*H, bnhb + (l-1)*H,
                                      l-1, l > 0 ? 1 : 0, n);

        agg_fused<<<G_NODE_W, TB>>>(C_w + l*H*H, C_b + l*H,
                                    bneg + (l-1)*H, bneb + (l-1)*H,
                                    l-1, l, l > 0 ? 1 : 0, n, inv_ne);
    }

    score_gemm2<<<G_NODE_W, TB>>>(W1_w, W1_b,
                                  bnhg + (NL-1)*H, bnhb + (NL-1)*H, NL-1, n);
    score_kernel<<<G_EDGE_W, TB>>>(dst, W1_w + 64*32, W2_w, W2_b,
                                   bneg + (NL-1)*H, bneb + (NL-1)*H, NL-1,
                                   out, ne, inv_ne);
}

// round 5
// speedup vs baseline: 1.3991x; 1.0668x over previous
#include <cuda_runtime.h>
#include <cuda_fp16.h>
#include <mma.h>
#include <math.h>

using namespace nvcuda;

#define NN 100000
#define EE 800000
#define H  32
#define NL 4
#define FULL 0xffffffffu
#define SCAN_N   (NN + 1)
#define SCAN_NB  ((SCAN_N + 1023) / 1024)

// ---------------- scratch ---------------------------------------------------------
__device__ float  g_h[NN*H];
__device__ float  g_hnew[NN*H];
__device__ float  g_Ah[NN*H];
__device__ float  g_Bh[NN*H];
__device__ float  g_Uh[NN*H];
__device__ float  g_Vh[NN*H];
__device__ __half g_e[EE*H];       // e_l (dst-sorted), updated in place by ce_mma
__device__ __half g_enew[EE*H];    // enew_l (dst-sorted)
__device__ float  g_ce[EE*H];      // Ce (fp32, tensor-core output)
// stats slots: per layer l: [l*128 + 0:64) h sum/sq, [l*128+64:128) e sum/sq
__device__ float  g_stats[NL*128];
__device__ int    g_hist[SCAN_NB*1024];
__device__ int    g_rowptr[NN+1];
__device__ int    g_cursor[NN];
__device__ int    g_bsum[SCAN_NB];
__device__ int    g_boff[SCAN_NB];
__device__ int    g_ssrc[EE];
__device__ int    g_oid[EE];

// ---------------- CSR build -------------------------------------------------------
__global__ void hist_kernel(const int* __restrict__ dst, int ne)
{
    for (int i = blockIdx.x * blockDim.x + threadIdx.x; i < ne;
         i += gridDim.x * blockDim.x)
        atomicAdd(&g_hist[dst[i]], 1);
}

__global__ void scanA()
{
    __shared__ int sm[1024];
    int idx = blockIdx.x * 1024 + threadIdx.x;
    int v = (idx < SCAN_N) ? g_hist[idx] : 0;
    sm[threadIdx.x] = v;
    __syncthreads();
    for (int off = 512; off > 0; off >>= 1) {
        if (threadIdx.x < off) sm[threadIdx.x] += sm[threadIdx.x + off];
        __syncthreads();
    }
    if (threadIdx.x == 0) g_bsum[blockIdx.x] = sm[0];
}

__global__ void scanB()
{
    __shared__ int sm[128];
    int t = threadIdx.x;
    sm[t] = (t < SCAN_NB) ? g_bsum[t] : 0;
    __syncthreads();
    for (int off = 1; off < 128; off <<= 1) {
        int v = (t >= off) ? sm[t - off] : 0;
        __syncthreads();
        sm[t] += v;
        __syncthreads();
    }
    if (t < SCAN_NB) g_boff[t] = sm[t] - g_bsum[t];
}

__global__ void scanC()
{
    __shared__ int sm[1024];
    int idx = blockIdx.x * 1024 + threadIdx.x;
    int t = threadIdx.x;
    int v = (idx < SCAN_N) ? g_hist[idx] : 0;
    sm[t] = v;
    __syncthreads();
    for (int off = 1; off < 1024; off <<= 1) {
        int u = (t >= off) ? sm[t - off] : 0;
        __syncthreads();
        sm[t] += u;
        __syncthreads();
    }
    if (idx < SCAN_N) {
        int excl = sm[t] - v + g_boff[blockIdx.x];
        g_rowptr[idx] = excl;
        if (idx < NN) g_cursor[idx] = excl;
    }
}

__global__ void scatter_kernel(const int* __restrict__ src, const int* __restrict__ dst,
                               int ne)
{
    for (int i = blockIdx.x * blockDim.x + threadIdx.x; i < ne;
         i += gridDim.x * blockDim.x) {
        int d = dst[i];
        int pos = atomicAdd(&g_cursor[d], 1);
        g_ssrc[pos] = src[i];
        g_oid[pos]  = i;
    }
}

// ---------------- input projections -----------------------------------------------
__global__ void proj_h(const float* __restrict__ x, const float* __restrict__ w,
                       const float* __restrict__ b, int n)
{
    int total = n * H;
    for (int t = blockIdx.x * blockDim.x + threadIdx.x; t < total;
         t += gridDim.x * blockDim.x) {
        int row = t >> 5, lane = t & 31;
        g_h[t] = x[row] * w[lane] + b[lane];
    }
}

__global__ void proj_e(const float* __restrict__ ein, const float* __restrict__ w,
                       const float* __restrict__ b, int ne)
{
    int total = ne * H;
    for (int t = blockIdx.x * blockDim.x + threadIdx.x; t < total;
         t += gridDim.x * blockDim.x) {
        int row = t >> 5, lane = t & 31;
        g_e[t] = __float2half_rn(ein[g_oid[row]] * w[lane] + b[lane]);
    }
}

// ------- gemm4, with h-update of previous layer fused (l>=1) ----------------------
__global__ void gemm4_fused(const float* __restrict__ Aw, const float* __restrict__ Ab,
                            const float* __restrict__ Bw, const float* __restrict__ Bb,
                            const float* __restrict__ Uw, const float* __restrict__ Ub,
                            const float* __restrict__ Vw, const float* __restrict__ Vb,
                            const float* __restrict__ bng, const float* __restrict__ bnb,
                            int statSlot, int applyUpd, int n)
{
    __shared__ float wA[H*H], wB[H*H], wU[H*H], wV[H*H];
    __shared__ float bA[H], bB[H], bU[H], bV[H];
    for (int i = threadIdx.x; i < H*H; i += blockDim.x) {
        wA[i] = Aw[i]; wB[i] = Bw[i]; wU[i] = Uw[i]; wV[i] = Vw[i];
    }
    if (threadIdx.x < H) {
        bA[threadIdx.x] = Ab[threadIdx.x];
        bB[threadIdx.x] = Bb[threadIdx.x];
        bU[threadIdx.x] = Ub[threadIdx.x];
        bV[threadIdx.x] = Vb[threadIdx.x];
    }
    __syncthreads();

    int lane = threadIdx.x & 31;
    float mn = 0.f, sc = 0.f, bt = 0.f;
    if (applyUpd) {
        float inv = 1.0f / (float)n;
        float s1 = g_stats[statSlot*128 + lane];
        float s2 = g_stats[statSlot*128 + 32 + lane];
        mn = s1 * inv;
        float var = s2 * inv - mn * mn;
        sc = rsqrtf(var + 1e-5f) * bng[lane];
        bt = bnb[lane];
    }

    int row = blockIdx.x * (blockDim.x >> 5) + (threadIdx.x >> 5);
    if (row >= n) return;
    float hv = g_h[row*H + lane];
    if (applyUpd) {
        float v = (g_hnew[row*H + lane] - mn) * sc + bt;
        hv += fmaxf(v, 0.f);
        g_h[row*H + lane] = hv;
    }
    float a = bA[lane], b = bB[lane], u = bU[lane], v = bV[lane];
    #pragma unroll
    for (int k = 0; k < H; k++) {
        float hk = __shfl_sync(FULL, hv, k);
        a += hk * wA[k*H + lane];
        b += hk * wB[k*H + lane];
        u += hk * wU[k*H + lane];
        v += hk * wV[k*H + lane];
    }
    g_Ah[row*H + lane] = a;
    g_Bh[row*H + lane] = b;
    g_Uh[row*H + lane] = u;
    g_Vh[row*H + lane] = v;
}

// ---- tensor-core edge GEMM, fused with e-update of previous layer ----------------
// ce[i] = e_upd[i] @ W + bias, where e_upd = e + relu(BN(enew)) (if applyUpd)
// W is fp32; split into hi/lo fp16 so weight quantization error ~2^-22.
__global__ void ce_mma(const float* __restrict__ W, const float* __restrict__ bias,
                       const float* __restrict__ bng, const float* __restrict__ bnb,
                       int prevSlot, int applyUpd, int ne, float inv_ne)
{
    __shared__ __half sWhi[32*32], sWlo[32*32];
    __shared__ __half sE[4][16*32];
    __shared__ float  sC[4][16*32];
    __shared__ float  sBias[32], sMn[32], sSc[32], sBt[32];

    int tid = threadIdx.x;
    for (int i = tid; i < 1024; i += 128) {
        float w = W[i];
        __half hi = __float2half_rn(w);
        sWhi[i] = hi;
        sWlo[i] = __float2half_rn(w - __half2float(hi));
    }
    if (tid < 32) {
        sBias[tid] = bias ? bias[tid] : 0.f;
        if (applyUpd) {
            float s1 = g_stats[prevSlot*128 + 64 + tid];
            float s2 = g_stats[prevSlot*128 + 96 + tid];
            float mean = s1 * inv_ne;
            float var  = s2 * inv_ne - mean * mean;
            sMn[tid] = mean;
            sSc[tid] = rsqrtf(var + 1e-5f) * bng[tid];
            sBt[tid] = bnb[tid];
        } else { sMn[tid] = 0.f; sSc[tid] = 0.f; sBt[tid] = 0.f; }
    }
    __syncthreads();

    int warp = tid >> 5, lane = tid & 31;

    wmma::fragment<wmma::matrix_b, 16,16,16, __half, wmma::row_major> bh[2][2], bl[2][2];
    #pragma unroll
    for (int kk = 0; kk < 2; kk++)
        #pragma unroll
        for (int nn = 0; nn < 2; nn++) {
            wmma::load_matrix_sync(bh[kk][nn], sWhi + kk*16*32 + nn*16, 32);
            wmma::load_matrix_sync(bl[kk][nn], sWlo + kk*16*32 + nn*16, 32);
        }

    __half2* e2 = (__half2*)g_e;
    const __half2* en2 = (const __half2*)g_enew;
    int ntiles = (ne + 63) >> 6;

    for (int t = blockIdx.x; t < ntiles; t += gridDim.x) {
        int rbase = t*64 + warp*16;   // this warp's 16 edge rows
        __half2* stage = (__half2*)sE[warp];
        // stage updated e tile (16 rows x 16 half2)
        #pragma unroll
        for (int i = 0; i < 8; i++) {
            int idx = i*32 + lane;           // 0..255 half2 slots
            int row = rbase + (idx >> 4);
            int ch  = idx & 15;              // half2 column
            if (row < ne) {
                size_t g = (size_t)row*16 + ch;
                __half2 ev = e2[g];
                if (applyUpd) {
                    float2 f  = __half22float2(ev);
                    float2 en = __half22float2(en2[g]);
                    int c = ch*2;
                    f.x += fmaxf((en.x - sMn[c])   * sSc[c]   + sBt[c],   0.f);
                    f.y += fmaxf((en.y - sMn[c+1]) * sSc[c+1] + sBt[c+1], 0.f);
                    __half2 nv = __floats2half2_rn(f.x, f.y);
                    e2[g] = nv;
                    stage[idx] = nv;
                } else {
                    stage[idx] = ev;
                }
            } else {
                stage[idx] = __floats2half2_rn(0.f, 0.f);
            }
        }
        __syncwarp();

        wmma::fragment<wmma::matrix_a, 16,16,16, __half, wmma::row_major> a0, a1;
        wmma::load_matrix_sync(a0, sE[warp],      32);
        wmma::load_matrix_sync(a1, sE[warp] + 16, 32);

        wmma::fragment<wmma::accumulator, 16,16,16, float> acc0, acc1;
        wmma::fill_fragment(acc0, 0.f);
        wmma::fill_fragment(acc1, 0.f);
        wmma::mma_sync(acc0, a0, bh[0][0], acc0);
        wmma::mma_sync(acc0, a1, bh[1][0], acc0);
        wmma::mma_sync(acc0, a0, bl[0][0], acc0);
        wmma::mma_sync(acc0, a1, bl[1][0], acc0);
        wmma::mma_sync(acc1, a0, bh[0][1], acc1);
        wmma::mma_sync(acc1, a1, bh[1][1], acc1);
        wmma::mma_sync(acc1, a0, bl[0][1], acc1);
        wmma::mma_sync(acc1, a1, bl[1][1], acc1);

        wmma::store_matrix_sync(sC[warp],      acc0, 32, wmma::mem_row_major);
        wmma::store_matrix_sync(sC[warp] + 16, acc1, 32, wmma::mem_row_major);
        __syncwarp();

        #pragma unroll
        for (int r = 0; r < 16; r++) {
            int row = rbase + r;
            if (row < ne)
                g_ce[(size_t)row*32 + lane] = sC[warp][r*32 + lane] + sBias[lane];
        }
        __syncwarp();
    }
}

// ---- aggregation: warp per node; no GEMM (ce precomputed); no atomics -----------
__global__ void agg2(int curSlot, int n)
{
    int lane = threadIdx.x & 31;

    __shared__ float sE[32], qE[32], sH[32], qH[32];
    if (threadIdx.x < 32) {
        sE[threadIdx.x] = 0.f; qE[threadIdx.x] = 0.f;
        sH[threadIdx.x] = 0.f; qH[threadIdx.x] = 0.f;
    }
    __syncthreads();

    float ls = 0.f, lq = 0.f, hs = 0.f, hq = 0.f;
    int d = blockIdx.x * (blockDim.x >> 5) + (threadIdx.x >> 5);
    if (d < n) {
        int beg = g_rowptr[d], end = g_rowptr[d+1];
        float ah = g_Ah[d*H + lane];
        float uh = g_Uh[d*H + lane];
        float num = 0.f, den = 0.f;
        int i = beg;
        for (; i + 1 < end; i += 2) {
            int s0 = g_ssrc[i], s1 = g_ssrc[i+1];
            float ce0 = g_ce[(size_t)i*H + lane];
            float ce1 = g_ce[(size_t)(i+1)*H + lane];
            float bh0 = g_Bh[s0*H + lane], bh1 = g_Bh[s1*H + lane];
            float vh0 = g_Vh[s0*H + lane], vh1 = g_Vh[s1*H + lane];
            float e0 = ah + bh0 + ce0;
            float e1 = ah + bh1 + ce1;
            g_enew[(size_t)i*H + lane]     = __float2half_rn(e0);
            g_enew[(size_t)(i+1)*H + lane] = __float2half_rn(e1);
            ls += e0 + e1;
            lq += e0 * e0 + e1 * e1;
            float sg0 = 1.0f / (1.0f + __expf(-e0));
            float sg1 = 1.0f / (1.0f + __expf(-e1));
            num += sg0 * vh0 + sg1 * vh1;
            den += sg0 + sg1;
        }
        for (; i < end; i++) {
            int s0 = g_ssrc[i];
            float e0 = ah + g_Bh[s0*H + lane] + g_ce[(size_t)i*H + lane];
            g_enew[(size_t)i*H + lane] = __float2half_rn(e0);
            ls += e0; lq += e0 * e0;
            float sg0 = 1.0f / (1.0f + __expf(-e0));
            num += sg0 * g_Vh[s0*H + lane];
            den += sg0;
        }
        float hn = uh + num / (den + 1e-6f);
        g_hnew[d*H + lane] = hn;
        hs += hn; hq += hn * hn;
    }
    atomicAdd(&sH[lane], hs); atomicAdd(&qH[lane], hq);
    atomicAdd(&sE[lane], ls); atomicAdd(&qE[lane], lq);
    __syncthreads();
    if (threadIdx.x < 32) {
        atomicAdd(&g_stats[curSlot*128 + threadIdx.x],      sH[threadIdx.x]);
        atomicAdd(&g_stats[curSlot*128 + 32 + threadIdx.x], qH[threadIdx.x]);
        atomicAdd(&g_stats[curSlot*128 + 64 + threadIdx.x], sE[threadIdx.x]);
        atomicAdd(&g_stats[curSlot*128 + 96 + threadIdx.x], qE[threadIdx.x]);
    }
}

// ---- score pre-pass: final h-update fused; hid_src -> g_Ah, hid_dst -> g_Bh ------
__global__ void score_gemm2(const float* __restrict__ W1, const float* __restrict__ b1,
                            const float* __restrict__ bng, const float* __restrict__ bnb,
                            int statSlot, int n)
{
    int lane = threadIdx.x & 31;
    float ws[32], wd[32];
    #pragma unroll
    for (int k = 0; k < 32; k++) {
        ws[k] = W1[k*32 + lane];
        wd[k] = W1[(32 + k)*32 + lane];
    }
    float bb = b1[lane];
    float inv = 1.0f / (float)n;
    float s1 = g_stats[statSlot*128 + lane];
    float s2 = g_stats[statSlot*128 + 32 + lane];
    float mn = s1 * inv;
    float var = s2 * inv - mn * mn;
    float sc = rsqrtf(var + 1e-5f) * bng[lane];
    float bt = bnb[lane];

    int row = blockIdx.x * (blockDim.x >> 5) + (threadIdx.x >> 5);
    if (row >= n) return;
    float hv = g_h[row*H + lane];
    hv += fmaxf((g_hnew[row*H + lane] - mn) * sc + bt, 0.f);
    float a = bb, c = 0.f;
    #pragma unroll
    for (int k = 0; k < 32; k++) {
        float hk = __shfl_sync(FULL, hv, k);
        a += hk * ws[k];
        c += hk * wd[k];
    }
    g_Ah[row*H + lane] = a;
    g_Bh[row*H + lane] = c;
}

// ---- score: hid = relu(hid_s + hid_d + hid_e); out = hid @ W2 + b2 ---------------
__global__ void score_final(const int* __restrict__ dst,
                            const float* __restrict__ W2, const float* __restrict__ b2,
                            float* __restrict__ out, int ne)
{
    int lane = threadIdx.x & 31;
    float w2 = W2[lane];
    float bb2 = b2[0];

    int i = blockIdx.x * (blockDim.x >> 5) + (threadIdx.x >> 5);
    if (i >= ne) return;
    int s = g_ssrc[i], o = g_oid[i];
    int d = dst[o];
    float hid = g_Ah[s*H + lane] + g_Bh[d*H + lane] + g_ce[(size_t)i*H + lane];
    hid = fmaxf(hid, 0.f);
    float p = hid * w2;
    #pragma unroll
    for (int off = 16; off > 0; off >>= 1)
        p += __shfl_xor_sync(FULL, p, off);
    if (lane == 0) out[o] = p + bb2;
}

// ==================================================================================
extern "C" void kernel_launch(void* const* d_in, const int* in_sizes, int n_in,
                              void* d_out, int out_size)
{
    const float* x    = (const float*)d_in[0];
    const float* ein  = (const float*)d_in[1];
    const int*   eidx = (const int*)  d_in[2];
    const float* pe_w = (const float*)d_in[3];
    const float* pe_b = (const float*)d_in[4];
    const float* ed_w = (const float*)d_in[5];
    const float* ed_b = (const float*)d_in[6];
    const float* A_w  = (const float*)d_in[7];
    const float* A_b  = (const float*)d_in[8];
    const float* B_w  = (const float*)d_in[9];
    const float* B_b  = (const float*)d_in[10];
    const float* C_w  = (const float*)d_in[11];
    const float* C_b  = (const float*)d_in[12];
    const float* U_w  = (const float*)d_in[13];
    const float* U_b  = (const float*)d_in[14];
    const float* V_w  = (const float*)d_in[15];
    const float* V_b  = (const float*)d_in[16];
    const float* bnhg = (const float*)d_in[17];
    const float* bnhb = (const float*)d_in[18];
    const float* bneg = (const float*)d_in[19];
    const float* bneb = (const float*)d_in[20];
    const float* W1_w = (const float*)d_in[21];
    const float* W1_b = (const float*)d_in[22];
    const float* W2_w = (const float*)d_in[23];
    const float* W2_b = (const float*)d_in[24];
    float* out = (float*)d_out;

    const int n  = in_sizes[0];
    const int ne = in_sizes[1];
    const int* src = eidx;
    const int* dst = eidx + ne;
    const float inv_ne = 1.0f / (float)ne;

    void *p_hist, *p_stats;
    cudaGetSymbolAddress(&p_hist,  g_hist);
    cudaGetSymbolAddress(&p_stats, g_stats);

    const int TB = 256;
    const int WPB = TB / 32;
    const int G_NODE_W = (n  + WPB - 1) / WPB;
    const int G_EDGE_W = (ne + WPB - 1) / WPB;
    const int G_MMA = 1480;

    // ---- CSR build (dst-sorted edge order) ----
    cudaMemsetAsync(p_hist,  0, SCAN_NB * 1024 * sizeof(int));
    cudaMemsetAsync(p_stats, 0, NL * 128 * sizeof(float));
    hist_kernel<<<800, TB>>>(dst, ne);
    scanA<<<SCAN_NB, 1024>>>();
    scanB<<<1, 128>>>();
    scanC<<<SCAN_NB, 1024>>>();
    scatter_kernel<<<800, TB>>>(src, dst, ne);

    // ---- input projections ----
    proj_h<<<1024, TB>>>(x, pe_w, pe_b, n);
    proj_e<<<4096, TB>>>(ein, ed_w, ed_b, ne);

    for (int l = 0; l < NL; l++) {
        gemm4_fused<<<G_NODE_W, TB>>>(A_w + l*H*H, A_b + l*H,
                                      B_w + l*H*H, B_b + l*H,
                                      U_w + l*H*H, U_b + l*H,
                                      V_w + l*H*H, V_b + l*H,
                                      bnhg + (l-1)*H, bnhb + (l-1)*H,
                                      l-1, l > 0 ? 1 : 0, n);

        ce_mma<<<G_MMA, 128>>>(C_w + l*H*H, C_b + l*H,
                               bneg + (l-1)*H, bneb + (l-1)*H,
                               l-1, l > 0 ? 1 : 0, ne, inv_ne);

        agg2<<<G_NODE_W, TB>>>(l, n);
    }

    score_gemm2<<<G_NODE_W, TB>>>(W1_w, W1_b,
                                  bnhg + (NL-1)*H, bnhb + (NL-1)*H, NL-1, n);
    // hid_e = e_final @ W1[64:96]; final e-update fused; no bias (b1 is in hid_src)
    ce_mma<<<G_MMA, 128>>>(W1_w + 64*32, (const float*)nullptr,
                           bneg + (NL-1)*H, bneb + (NL-1)*H,
                           NL-1, 1, ne, inv_ne);
    score_final<<<G_EDGE_W, TB>>>(dst, W2_w, W2_b, out, ne);
}